// round 8
// baseline (speedup 1.0000x reference)
#include <cuda_runtime.h>
#include <math.h>

#define NB   16
#define HH   160
#define WW   160
#define HW   (HH*WW)
#define TOPK 32
#define CAP  3584
#define NBINS 2048
#define MAXM 1024
#define NV   68
#define RAD2DEG 57.29577951308232f
#define GPITCH 208
#define GRID_BLOCKS 128

// ---- device globals (zero-init; deterministic across replays) ----
__device__ unsigned long long g_cand[NB*CAP];
__device__ int   g_hist[NB*NBINS];   // re-zeroed each call in phase B
__device__ int   g_cnt[NB];          // idem
__device__ float g_scores[NB*TOPK];
__device__ int   g_idxs[NB*TOPK];
__device__ float gcbT[80*GPITCH];    // transposed combined basis (rewritten each call)
__device__ float g_bbox[NB*TOPK*5];
__device__ float g_pose[NB*TOPK*3];
__device__ float g_lnm[NB*TOPK*NV*2];
__device__ float g_peaks[NB*HW];     // fallback scratch only
__device__ unsigned bar_cnt[4];      // resets to 0 each use
__device__ unsigned bar_rel[4];      // monotonically increasing (behavior independent of value)

// ---- software grid barrier (threadfence + ticket/release) ----
__device__ __forceinline__ void grid_barrier(int id) {
    __threadfence();          // make this thread's global writes visible GPU-wide
    __syncthreads();
    if (threadIdx.x == 0) {
        unsigned gen = *((volatile unsigned*)&bar_rel[id]);
        __threadfence();
        unsigned ticket = atomicAdd(&bar_cnt[id], 1);
        if (ticket == GRID_BLOCKS - 1) {
            *((volatile unsigned*)&bar_cnt[id]) = 0;   // safe: all arrived
            __threadfence();
            atomicAdd(&bar_rel[id], 1);
        } else {
            while (*((volatile unsigned*)&bar_rel[id]) == gen) __nanosleep(64);
        }
        __threadfence();
    }
    __syncthreads();
}

__global__ void __launch_bounds__(256) mega_kernel(
    const float* __restrict__ hms,
    const float* __restrict__ pmaps,
    const float* __restrict__ oshapes,
    const float* __restrict__ pms,
    const float* __restrict__ u_base,
    const float* __restrict__ shp_base,
    const float* __restrict__ exp_base,
    float* __restrict__ out)
{
    int blk  = blockIdx.x;
    int tid  = threadIdx.x;
    int lane = tid & 31;
    int wid  = tid >> 5;

    __shared__ __align__(16) char sbuf[17920];
    __shared__ int coarse[64];
    __shared__ int s_cnt, s_m, s_bstar, s_fast;
    __shared__ float rv[8];
    __shared__ int   rid[8];
    __shared__ float s_sc4[4];
    __shared__ int   s_ix4[4];
    __shared__ unsigned ssupp;
    __shared__ int svalid[TOPK], smatch[TOPK];

    // ================= PHASE A: peak scan (all 128 blocks) + basis transpose =================
    {
        int b    = blk >> 3;
        int band = blk & 7;
        const float* h = hms + (size_t)b * HW;
        const float NEG = -1e30f;
        for (int c = tid; c < 20 * 40; c += 256) {
            int row = c / 40;
            int x0  = (c - row * 40) * 4;
            int y   = band * 20 + row;
            int px  = y * WW + x0;
            int ym = (y > 0)      ? y - 1 : y;
            int yp = (y < HH - 1) ? y + 1 : y;
            float4 a0 = *(const float4*)(h + (size_t)ym * WW + x0);
            float4 a1 = *(const float4*)(h + (size_t)y  * WW + x0);
            float4 a2 = *(const float4*)(h + (size_t)yp * WW + x0);
            float m0 = fmaxf(a1.x, fmaxf(a0.x, a2.x));
            float m1 = fmaxf(a1.y, fmaxf(a0.y, a2.y));
            float m2 = fmaxf(a1.z, fmaxf(a0.z, a2.z));
            float m3 = fmaxf(a1.w, fmaxf(a0.w, a2.w));
            float lm = NEG, rm = NEG;
            if (x0 > 0) {
                int xl = x0 - 1;
                lm = fmaxf(h[(size_t)y * WW + xl], fmaxf(h[(size_t)ym * WW + xl], h[(size_t)yp * WW + xl]));
            }
            if (x0 + 4 < WW) {
                int xr = x0 + 4;
                rm = fmaxf(h[(size_t)y * WW + xr], fmaxf(h[(size_t)ym * WW + xr], h[(size_t)yp * WW + xr]));
            }
            float p0 = (fmaxf(lm, fmaxf(m0, m1)) == a1.x) ? a1.x : 0.0f;
            float p1 = (fmaxf(m0, fmaxf(m1, m2)) == a1.y) ? a1.y : 0.0f;
            float p2 = (fmaxf(m1, fmaxf(m2, m3)) == a1.z) ? a1.z : 0.0f;
            float p3 = (fmaxf(m2, fmaxf(m3, rm)) == a1.w) ? a1.w : 0.0f;

            float pv[4] = {p0, p1, p2, p3};
            #pragma unroll
            for (int j = 0; j < 4; j++) {
                bool has = pv[j] > 0.0f;
                unsigned bal = __ballot_sync(0xffffffffu, has);
                if (bal) {
                    int leader = __ffs(bal) - 1;
                    int base = 0;
                    if (lane == leader) base = atomicAdd(&g_cnt[b], __popc(bal));
                    base = __shfl_sync(0xffffffffu, base, leader);
                    if (has) {
                        int pos = base + __popc(bal & ((1u << lane) - 1u));
                        if (pos < CAP) {
                            g_cand[(size_t)b * CAP + pos] =
                                ((unsigned long long)__float_as_uint(pv[j]) << 20)
                                | (unsigned)(HW - (px + j));
                        }
                        int bin = min((int)(pv[j] * (float)NBINS), NBINS - 1);
                        atomicAdd(&g_hist[b * NBINS + bin], 1);
                    }
                }
            }
        }
        // basis transpose: block handles rows blk and blk+128
        for (int q = 0; q < 2; q++) {
            int r = blk + q * 128;
            if (r < 204 && tid < 80) {
                int k = tid;
                float v = (k < 50) ? shp_base[r * 50 + k]
                        : (k < 79) ? exp_base[r * 29 + (k - 50)]
                                   : u_base[r];
                gcbT[k * GPITCH + r] = v;
            }
        }
    }
    grid_barrier(0);

    // ================= PHASE B: per-batch select (blocks 0..15) =================
    if (blk < NB) {
        int b = blk;
        unsigned long long* keys = (unsigned long long*)sbuf;          // 8KB
        int* shist = (int*)(sbuf + 8192);                               // 8KB

        if (tid == 0) { s_cnt = g_cnt[b]; s_m = 0; }
        for (int i = tid; i < NBINS; i += 256) shist[i] = g_hist[b * NBINS + i];
        __syncthreads();
        for (int i = tid; i < NBINS; i += 256) g_hist[b * NBINS + i] = 0;
        if (tid == 0) g_cnt[b] = 0;

        int cnt = s_cnt;
        bool candfast = (cnt >= TOPK) && (cnt <= CAP);

        if (candfast) {
            if (tid < 64) {
                int s = 0;
                #pragma unroll
                for (int k = 0; k < 32; k++) s += shist[tid * 32 + k];
                coarse[tid] = s;
            }
            __syncthreads();
            if (tid == 0) {
                int cum = 0, cb = 63;
                for (; cb >= 0; cb--) { cum += coarse[cb]; if (cum >= TOPK) break; }
                if (cb < 0) cb = 0;
                int above = cum - coarse[cb];
                int bin = cb * 32 + 31;
                for (; bin >= cb * 32; bin--) {
                    above += shist[bin];
                    if (above >= TOPK) break;
                }
                if (bin < cb * 32) bin = cb * 32;
                s_bstar = bin;
                s_fast  = (above <= MAXM) ? 1 : 0;
            }
            __syncthreads();
            if (s_fast) {
                int bstar = s_bstar;
                for (int i = tid; i < cnt; i += 256) {
                    unsigned long long key = g_cand[(size_t)b * CAP + i];
                    float v = __uint_as_float((unsigned)(key >> 20));
                    int bin = min((int)(v * (float)NBINS), NBINS - 1);
                    if (bin >= bstar) {
                        int pos = atomicAdd(&s_m, 1);
                        keys[pos] = key;
                    }
                }
            }
        } else {
            if (tid == 0) s_fast = 0;
            __syncthreads();
        }
        __syncthreads();

        if (s_fast) {
            int M = s_m;
            for (int t = tid; t < M; t += 256) {
                unsigned long long kt = keys[t];
                int rank = 0;
                for (int i = 0; i < M; i++) rank += (keys[i] > kt) ? 1 : 0;
                if (rank < TOPK) {
                    g_scores[b * TOPK + rank] = __uint_as_float((unsigned)(kt >> 20));
                    g_idxs[b * TOPK + rank]   = HW - (int)(kt & 0xFFFFFull);
                }
            }
        } else {
            // robust fallback
            const float* h = hms + (size_t)b * HW;
            float* pk = g_peaks + (size_t)b * HW;
            for (int i = tid; i < HW; i += 256) {
                int y = i / WW, x = i - y * WW;
                float v = h[i], m = v;
                int y0 = (y > 0) ? y - 1 : y, y1 = (y < HH - 1) ? y + 1 : y;
                int x0 = (x > 0) ? x - 1 : x, x1 = (x < WW - 1) ? x + 1 : x;
                for (int yy = y0; yy <= y1; yy++)
                    for (int xx = x0; xx <= x1; xx++)
                        m = fmaxf(m, h[yy * WW + xx]);
                pk[i] = (v == m) ? v : 0.0f;
            }
            __syncthreads();
            for (int r = 0; r < TOPK; r++) {
                float bv = -2.0f; int bi = 0x3fffffff;
                for (int i = tid; i < HW; i += 256) {
                    float v = pk[i];
                    if (v > bv || (v == bv && i < bi)) { bv = v; bi = i; }
                }
                #pragma unroll
                for (int o = 16; o; o >>= 1) {
                    float v2 = __shfl_down_sync(0xffffffffu, bv, o);
                    int   i2 = __shfl_down_sync(0xffffffffu, bi, o);
                    if (v2 > bv || (v2 == bv && i2 < bi)) { bv = v2; bi = i2; }
                }
                if (lane == 0) { rv[wid] = bv; rid[wid] = bi; }
                __syncthreads();
                if (tid < 8) {
                    bv = rv[tid]; bi = rid[tid];
                    #pragma unroll
                    for (int o = 4; o; o >>= 1) {
                        float v2 = __shfl_down_sync(0xffu, bv, o);
                        int   i2 = __shfl_down_sync(0xffu, bi, o);
                        if (v2 > bv || (v2 == bv && i2 < bi)) { bv = v2; bi = i2; }
                    }
                    if (tid == 0) { g_scores[b * TOPK + r] = bv; g_idxs[b * TOPK + r] = bi; pk[bi] = -1.0f; }
                }
                __syncthreads();
            }
        }
    }
    grid_barrier(1);

    // ================= PHASE C: geometry (all 128 blocks; 4 dets each) =================
    {
        int b    = blk >> 3;
        int det0 = (blk & 7) * 4;
        float (*cT)[4]    = (float(*)[4])sbuf;                    // 80*4*4 = 1280
        float (*smisc)[12] = (float(*)[12])(sbuf + 1280);          // 192
        float (*sverts)[GPITCH] = (float(*)[GPITCH])(sbuf + 1472); // 3328
        float (*slnm)[137] = (float(*)[137])(sbuf + 4800);         // 2192

        if (tid < 4) {
            s_sc4[tid] = g_scores[b * TOPK + det0 + tid];
            s_ix4[tid] = g_idxs[b * TOPK + det0 + tid];
        }
        __syncthreads();

        for (int e = tid; e < 4 * 91; e += 256) {
            int det = e / 91, j = e - det * 91;
            float v = fmaf(pmaps[((size_t)b * HW + (size_t)s_ix4[det]) * 91 + j],
                           pms[91 + j], pms[j]);
            if (j < 12)      smisc[det][j] = v;
            else if (j < 62) cT[j - 12][det] = v;
            else             cT[50 + (j - 62)][det] = v;
        }
        __syncthreads();

        if (tid < 204) {
            int row = tid;
            float u = u_base[row];
            float a0 = u, a1 = u, a2 = u, a3 = u;
            #pragma unroll 4
            for (int k = 0; k < 79; k++) {
                float bv = gcbT[k * GPITCH + row];
                float4 c = *(const float4*)&cT[k][0];
                a0 = fmaf(bv, c.x, a0);
                a1 = fmaf(bv, c.y, a1);
                a2 = fmaf(bv, c.z, a2);
                a3 = fmaf(bv, c.w, a3);
            }
            sverts[0][row] = a0;
            sverts[1][row] = a1;
            sverts[2][row] = a2;
            sverts[3][row] = a3;
        }
        __syncthreads();

        float ry = oshapes[b * 2 + 0] * (1.0f / 160.0f);
        float rx = oshapes[b * 2 + 1] * (1.0f / 160.0f);
        for (int e = tid; e < 4 * NV; e += 256) {
            int det = e / NV, v = e - det * NV;
            const float* p = smisc[det];
            float s  = p[0];
            float vx = sverts[det][3 * v], vy = sverts[det][3 * v + 1], vz = sverts[det][3 * v + 2];
            float l0 = s * (vx * p[1] + vy * p[2] + vz * p[3]);
            float l1 = s * (vx * p[5] + vy * p[6] + vz * p[7]);
            int idx = s_ix4[det];
            int ys = idx / WW, xs = idx - (idx / WW) * WW;
            float yy = l1 + (float)ys * ry;
            float xx = l0 + (float)xs * rx;
            slnm[det][2 * v]     = yy;
            slnm[det][2 * v + 1] = xx;
            size_t gd = (size_t)(b * TOPK + det0 + det);
            g_lnm[(gd * NV + v) * 2 + 0] = yy;
            g_lnm[(gd * NV + v) * 2 + 1] = xx;
        }
        __syncthreads();

        if (wid < 4) {
            int det = wid;
            float ymn = 1e30f, ymx = -1e30f, xmn = 1e30f, xmx = -1e30f;
            for (int v = lane; v < NV; v += 32) {
                float yy = slnm[det][2 * v], xx = slnm[det][2 * v + 1];
                ymn = fminf(ymn, yy); ymx = fmaxf(ymx, yy);
                xmn = fminf(xmn, xx); xmx = fmaxf(xmx, xx);
            }
            #pragma unroll
            for (int o = 16; o; o >>= 1) {
                ymn = fminf(ymn, __shfl_down_sync(0xffffffffu, ymn, o));
                ymx = fmaxf(ymx, __shfl_down_sync(0xffffffffu, ymx, o));
                xmn = fminf(xmn, __shfl_down_sync(0xffffffffu, xmn, o));
                xmx = fmaxf(xmx, __shfl_down_sync(0xffffffffu, xmx, o));
            }
            if (lane == 0) {
                size_t gd = (size_t)(b * TOPK + det0 + det);
                bool mask = s_sc4[det] > 0.5f;
                float* bb = g_bbox + gd * 5;
                if (mask) { bb[0] = ymn; bb[1] = xmn; bb[2] = ymx; bb[3] = xmx; bb[4] = s_sc4[det]; }
                else      { bb[0] = -1.0f; bb[1] = -1.0f; bb[2] = -1.0f; bb[3] = -1.0f; bb[4] = -1.0f; }

                const float* p = smisc[det];
                float yaw   = asinf(-p[9]) * RAD2DEG;
                float cyw   = cosf(yaw);   // faithful: cos of yaw in DEGREES
                float pitch = atan2f(p[10] / cyw, p[11] / cyw) * RAD2DEG;
                float roll  = atan2f(p[5] / cyw, p[1] / cyw) * RAD2DEG;
                float* pp = g_pose + gd * 3;
                pp[0] = pitch; pp[1] = yaw; pp[2] = roll;
            }
        }
    }
    grid_barrier(2);

    // ================= PHASE D: NMS + pack (blocks 0..15) =================
    if (blk < NB) {
        int b = blk;
        float (*sbb)[5]  = (float(*)[5])sbuf;                  // 640
        float (*sob)[4]  = (float(*)[4])(sbuf + 640);          // 512
        float* sosc      = (float*)(sbuf + 1152);              // 128
        unsigned* rowm   = (unsigned*)(sbuf + 1280);           // 128

        if (tid < TOPK * 5) {
            int k = tid / 5, c = tid - k * 5;
            sbb[k][c] = g_bbox[((size_t)b * TOPK + k) * 5 + c];
        }
        if (tid < TOPK) { sosc[tid] = 0.0f; sob[tid][0] = 0.0f; sob[tid][1] = 0.0f; sob[tid][2] = 0.0f; sob[tid][3] = 0.0f; }
        __syncthreads();

        // parallel IoU row-masks: lane i -> bits of j>i with iou(i,j)>thr
        if (tid < 32) {
            int i = tid;
            float i0 = sbb[i][0], i1 = sbb[i][1], i2 = sbb[i][2], i3 = sbb[i][3];
            float ia = (i2 - i0) * (i3 - i1);
            unsigned m = 0;
            for (int j = 0; j < TOPK; j++) {
                float j0 = sbb[j][0], j1 = sbb[j][1], j2 = sbb[j][2], j3 = sbb[j][3];
                float ja = (j2 - j0) * (j3 - j1);
                float yy = fminf(i2, j2) - fmaxf(i0, j0);
                float xx = fminf(i3, j3) - fmaxf(i1, j1);
                float inter = fmaxf(yy, 0.0f) * fmaxf(xx, 0.0f);
                float uni   = ia + ja - inter;
                float iou   = inter / fmaxf(uni, 1e-8f);
                if (iou > 0.4f && j > i) m |= (1u << j);
            }
            rowm[i] = m;
        }
        __syncthreads();
        if (tid == 0) {
            unsigned supp = 0u;
            for (int i = 0; i < TOPK; i++)
                if (!((supp >> i) & 1u)) supp |= rowm[i];
            ssupp = supp;
        }
        __syncthreads();

        if (tid < 32) {
            unsigned supp = ssupp;
            bool keep = !((supp >> lane) & 1u);
            unsigned km = __ballot_sync(0xffffffffu, keep);
            int rank = __popc(km & ((1u << lane) - 1u));
            if (keep) {
                sob[rank][0] = sbb[lane][0]; sob[rank][1] = sbb[lane][1];
                sob[rank][2] = sbb[lane][2]; sob[rank][3] = sbb[lane][3];
                sosc[rank]   = sbb[lane][4];
            }
        }
        __syncthreads();

        const float INF = __int_as_float(0x7f800000);
        if (tid < TOPK) {
            bool valid = true;
            #pragma unroll
            for (int c = 0; c < 4; c++) {
                float v = sob[tid][c];
                if (v == -1.0f || v == 0.0f) { v = INF; valid = false; }
                sob[tid][c] = v;
            }
            svalid[tid] = valid ? 1 : 0;
        }
        __syncthreads();
        if (tid < TOPK) {
            float sn = g_scores[b * TOPK + tid];
            int m = 0;
            for (int k = 0; k < TOPK; k++)
                if (svalid[k] && sosc[k] == sn) m = 1;
            smatch[tid] = m;
        }
        __syncthreads();

        float* ob = out + (size_t)b * TOPK * 6;
        for (int e = tid; e < TOPK * 6; e += 256) {
            int k = e / 6, c = e - k * 6;
            ob[e] = (c < 4) ? sob[k][c] : ((c == 4) ? sosc[k] : 0.0f);
        }
        float* ol = out + (size_t)NB * TOPK * 6 + (size_t)b * TOPK * NV * 2;
        for (int e = tid; e < TOPK * NV * 2; e += 256) {
            int n = e / (NV * 2);
            float l = g_lnm[(size_t)b * TOPK * NV * 2 + e];
            ol[e] = (smatch[n] && l != -1.0f) ? l : INF;
        }
        float* op = out + (size_t)NB * TOPK * 6 + (size_t)NB * TOPK * NV * 2 + (size_t)b * TOPK * 3;
        for (int e = tid; e < TOPK * 3; e += 256) {
            int n = e / 3;
            float p = g_pose[(size_t)b * TOPK * 3 + e];
            op[e] = (smatch[n] && p != -1.0f) ? p : INF;
        }
    }
}

extern "C" void kernel_launch(void* const* d_in, const int* in_sizes, int n_in,
                              void* d_out, int out_size) {
    const float* hms      = (const float*)d_in[0];
    const float* pmaps    = (const float*)d_in[1];
    const float* oshapes  = (const float*)d_in[2];
    const float* pms      = (const float*)d_in[3];
    const float* u_base   = (const float*)d_in[4];
    const float* shp_base = (const float*)d_in[5];
    const float* exp_base = (const float*)d_in[6];
    float* out = (float*)d_out;

    mega_kernel<<<GRID_BLOCKS, 256>>>(hms, pmaps, oshapes, pms, u_base, shp_base, exp_base, out);
}

// round 9
// speedup vs baseline: 1.2522x; 1.2522x over previous
#include <cuda_runtime.h>
#include <math.h>

#define NB   16
#define HH   160
#define WW   160
#define HW   (HH*WW)
#define TOPK 32
#define NV   68
#define RAD2DEG 57.29577951308232f
#define GPITCH 208
#define BCAP 1024

// ---- device globals (zero-init; deterministic across replays) ----
__device__ unsigned long long g_bandtop[NB*8*TOPK];  // fully rewritten each call
__device__ int   g_cnt[NB];          // accumulated in scan, reset in finish
__device__ int   g_ovf[NB];          // idem
__device__ float gcbT[80*GPITCH];    // transposed combined basis (rewritten each call)
__device__ float g_peaks[NB*HW];     // fallback scratch only

#define PACK_DUP(out, f) asm("mov.b64 %0, {%1, %1};" : "=l"(out) : "r"(__float_as_uint(f)))
#define FMA2(acc, bb, cc)  asm("fma.rn.f32x2 %0, %1, %2, %0;" : "+l"(acc) : "l"(bb), "l"(cc))
#define UNPACK2(lo, hi, in) asm("mov.b64 {%0, %1}, %2;" : "=r"(lo), "=r"(hi) : "l"(in))

// ============================================================
// Kernel 1 (WIDE, 128 blocks x 256): peak scan + per-band top-32
// + basis transpose. No histogram, no global candidate list.
// ============================================================
__global__ void __launch_bounds__(256) scan_kernel(
    const float* __restrict__ hms,
    const float* __restrict__ u_base,
    const float* __restrict__ shp_base,
    const float* __restrict__ exp_base)
{
    int blk  = blockIdx.x;
    int b    = blk >> 3;
    int band = blk & 7;
    int tid  = threadIdx.x;
    int lane = tid & 31;
    const float* h = hms + (size_t)b * HW;

    __shared__ unsigned long long bk[BCAP];
    __shared__ int s_cnt;

    if (tid == 0) s_cnt = 0;
    // basis transpose: rows blk and blk+128
    #pragma unroll
    for (int q = 0; q < 2; q++) {
        int r = blk + q * 128;
        if (r < 204 && tid < 80) {
            int k = tid;
            float v = (k < 50) ? shp_base[r * 50 + k]
                    : (k < 79) ? exp_base[r * 29 + (k - 50)]
                               : u_base[r];
            gcbT[k * GPITCH + r] = v;
        }
    }
    __syncthreads();

    const float NEG = -1e30f;
    for (int c = tid; c < 20 * 40; c += 256) {
        int row = c / 40;
        int x0  = (c - row * 40) * 4;
        int y   = band * 20 + row;
        int px  = y * WW + x0;
        int ym = (y > 0)      ? y - 1 : y;
        int yp = (y < HH - 1) ? y + 1 : y;
        float4 a0 = *(const float4*)(h + (size_t)ym * WW + x0);
        float4 a1 = *(const float4*)(h + (size_t)y  * WW + x0);
        float4 a2 = *(const float4*)(h + (size_t)yp * WW + x0);
        float m0 = fmaxf(a1.x, fmaxf(a0.x, a2.x));
        float m1 = fmaxf(a1.y, fmaxf(a0.y, a2.y));
        float m2 = fmaxf(a1.z, fmaxf(a0.z, a2.z));
        float m3 = fmaxf(a1.w, fmaxf(a0.w, a2.w));
        float lm = NEG, rm = NEG;
        if (x0 > 0) {
            int xl = x0 - 1;
            lm = fmaxf(h[(size_t)y * WW + xl], fmaxf(h[(size_t)ym * WW + xl], h[(size_t)yp * WW + xl]));
        }
        if (x0 + 4 < WW) {
            int xr = x0 + 4;
            rm = fmaxf(h[(size_t)y * WW + xr], fmaxf(h[(size_t)ym * WW + xr], h[(size_t)yp * WW + xr]));
        }
        float p0 = (fmaxf(lm, fmaxf(m0, m1)) == a1.x) ? a1.x : 0.0f;
        float p1 = (fmaxf(m0, fmaxf(m1, m2)) == a1.y) ? a1.y : 0.0f;
        float p2 = (fmaxf(m1, fmaxf(m2, m3)) == a1.z) ? a1.z : 0.0f;
        float p3 = (fmaxf(m2, fmaxf(m3, rm)) == a1.w) ? a1.w : 0.0f;

        float pv[4] = {p0, p1, p2, p3};
        #pragma unroll
        for (int j = 0; j < 4; j++) {
            bool has = pv[j] > 0.0f;
            unsigned bal = __ballot_sync(0xffffffffu, has);
            if (bal) {
                int leader = __ffs(bal) - 1;
                int base = 0;
                if (lane == leader) base = atomicAdd(&s_cnt, __popc(bal));
                base = __shfl_sync(0xffffffffu, base, leader);
                if (has) {
                    int pos = base + __popc(bal & ((1u << lane) - 1u));
                    if (pos < BCAP)
                        bk[pos] = ((unsigned long long)__float_as_uint(pv[j]) << 20)
                                | (unsigned)(HW - (px + j));
                }
            }
        }
    }
    __syncthreads();

    int cnt = s_cnt;
    unsigned long long* bt = &g_bandtop[(size_t)(b * 8 + band) * TOPK];
    if (tid == 0) {
        atomicAdd(&g_cnt[b], cnt);
        if (cnt > BCAP) g_ovf[b] = 1;
    }
    if (tid < TOPK) bt[tid] = 0ull;     // zeros for slots >= cnt
    __syncthreads();

    if (cnt <= BCAP) {
        // parallel rank-select: band top-32 (exact, tie-break encoded in key)
        for (int t = tid; t < cnt; t += 256) {
            unsigned long long kt = bk[t];
            int rank = 0;
            #pragma unroll 4
            for (int i = 0; i < cnt; i++) rank += (bk[i] > kt) ? 1 : 0;
            if (rank < TOPK) bt[rank] = kt;
        }
    }
}

// ---- finish kernel dynamic shared layout (bytes) ----
#define F_KEYS   0                      // u64[256]            2048
#define F_CT     2048                   // float[4][80][8]    10240
#define F_MISC   12288                  // float[32][12]       1536
#define F_SV     13824                  // float[32][205]     26240
#define F_SL     40064                  // float[32][137]     17536
#define F_DSM    57600
#define SVP 205
#define SLP 137

// ============================================================
// Kernel 2 (16 blocks x 1024): merge->top32, geometry, NMS, pack.
// Everything after the merge is shared-resident.
// ============================================================
__global__ void __launch_bounds__(1024) finish_kernel(
    const float* __restrict__ hms,
    const float* __restrict__ pmaps,
    const float* __restrict__ oshapes,
    const float* __restrict__ pms,
    const float* __restrict__ u_base,
    float* __restrict__ out)
{
    extern __shared__ char sbuf[];
    int b    = blockIdx.x;
    int tid  = threadIdx.x;
    int lane = tid & 31;
    int wid  = tid >> 5;

    unsigned long long* keys = (unsigned long long*)(sbuf + F_KEYS);
    float* cT     = (float*)(sbuf + F_CT);
    float* smisc  = (float*)(sbuf + F_MISC);
    float* sverts = (float*)(sbuf + F_SV);
    float* slnm   = (float*)(sbuf + F_SL);

    __shared__ float s_sc[TOPK];
    __shared__ int   s_ix[TOPK];
    __shared__ float sbb[TOPK][5];
    __shared__ float spose[TOPK][3];
    __shared__ float sob[TOPK][4], sosc[TOPK];
    __shared__ int   svalid[TOPK], smatch[TOPK];
    __shared__ int   s_fast;
    __shared__ unsigned ssupp;
    __shared__ float rv[32];
    __shared__ int   rid[32];

    if (tid < 256) keys[tid] = g_bandtop[(size_t)b * 256 + tid];
    if (tid == 0) {
        int c = g_cnt[b], o = g_ovf[b];
        s_fast = (c >= TOPK && !o) ? 1 : 0;
        g_cnt[b] = 0; g_ovf[b] = 0;     // restore zero-state invariant
    }
    __syncthreads();

    if (s_fast) {
        if (tid < 256) {
            unsigned long long kt = keys[tid];
            int rank = 0;
            #pragma unroll 8
            for (int i = 0; i < 256; i++) rank += (keys[i] > kt) ? 1 : 0;
            if (rank < TOPK) {
                s_sc[rank] = __uint_as_float((unsigned)(kt >> 20));
                s_ix[rank] = HW - (int)(kt & 0xFFFFFull);
            }
        }
    } else {
        // robust fallback: recompute peaks, 32 block argmax rounds
        const float* h = hms + (size_t)b * HW;
        float* pk = g_peaks + (size_t)b * HW;
        for (int i = tid; i < HW; i += 1024) {
            int y = i / WW, x = i - y * WW;
            float v = h[i], m = v;
            int y0 = (y > 0) ? y - 1 : y, y1 = (y < HH - 1) ? y + 1 : y;
            int x0 = (x > 0) ? x - 1 : x, x1 = (x < WW - 1) ? x + 1 : x;
            for (int yy = y0; yy <= y1; yy++)
                for (int xx = x0; xx <= x1; xx++)
                    m = fmaxf(m, h[yy * WW + xx]);
            pk[i] = (v == m) ? v : 0.0f;
        }
        __syncthreads();
        for (int r = 0; r < TOPK; r++) {
            float bv = -2.0f; int bi = 0x3fffffff;
            for (int i = tid; i < HW; i += 1024) {
                float v = pk[i];
                if (v > bv || (v == bv && i < bi)) { bv = v; bi = i; }
            }
            #pragma unroll
            for (int o = 16; o; o >>= 1) {
                float v2 = __shfl_down_sync(0xffffffffu, bv, o);
                int   i2 = __shfl_down_sync(0xffffffffu, bi, o);
                if (v2 > bv || (v2 == bv && i2 < bi)) { bv = v2; bi = i2; }
            }
            if (lane == 0) { rv[wid] = bv; rid[wid] = bi; }
            __syncthreads();
            if (tid < 32) {
                bv = rv[lane]; bi = rid[lane];
                #pragma unroll
                for (int o = 16; o; o >>= 1) {
                    float v2 = __shfl_down_sync(0xffffffffu, bv, o);
                    int   i2 = __shfl_down_sync(0xffffffffu, bi, o);
                    if (v2 > bv || (v2 == bv && i2 < bi)) { bv = v2; bi = i2; }
                }
                if (lane == 0) { s_sc[r] = bv; s_ix[r] = bi; pk[bi] = -1.0f; }
            }
            __syncthreads();
        }
    }
    __syncthreads();

    // ---- gather + denorm params: cT[grp][k][det8] + smisc ----
    for (int e = tid; e < TOPK * 91; e += 1024) {
        int det = e / 91, j = e - det * 91;
        float v = fmaf(pmaps[((size_t)b * HW + (size_t)s_ix[det]) * 91 + j],
                       pms[91 + j], pms[j]);
        if (j < 12) smisc[det * 12 + j] = v;
        else {
            int k = (j < 62) ? (j - 12) : (50 + (j - 62));
            int grp = det >> 3, d = det & 7;
            cT[grp * 640 + k * 8 + d] = v;
        }
    }
    __syncthreads();

    // ---- verts: 4 groups x 256 threads; thread = row; f32x2 packed ----
    {
        int grp = tid >> 8;
        int r   = tid & 255;
        if (r < 204) {
            float u = u_base[r];
            unsigned long long ud; PACK_DUP(ud, u);
            unsigned long long acc0 = ud, acc1 = ud, acc2 = ud, acc3 = ud;
            const ulonglong2* ct64 = (const ulonglong2*)(cT + grp * 640);
            #pragma unroll 4
            for (int k = 0; k < 79; k++) {
                float bv = gcbT[k * GPITCH + r];
                unsigned long long bd; PACK_DUP(bd, bv);
                ulonglong2 c0 = ct64[k * 2];       // dets 0-3
                ulonglong2 c1 = ct64[k * 2 + 1];   // dets 4-7
                FMA2(acc0, bd, c0.x);
                FMA2(acc1, bd, c0.y);
                FMA2(acc2, bd, c1.x);
                FMA2(acc3, bd, c1.y);
            }
            unsigned av[8];
            UNPACK2(av[0], av[1], acc0);
            UNPACK2(av[2], av[3], acc1);
            UNPACK2(av[4], av[5], acc2);
            UNPACK2(av[6], av[7], acc3);
            #pragma unroll
            for (int d = 0; d < 8; d++)
                sverts[(grp * 8 + d) * SVP + r] = __uint_as_float(av[d]);
        }
    }
    __syncthreads();

    // ---- landmark projection ----
    float ry = oshapes[b * 2 + 0] * (1.0f / 160.0f);
    float rx = oshapes[b * 2 + 1] * (1.0f / 160.0f);
    for (int e = tid; e < TOPK * NV; e += 1024) {
        int det = e & 31;
        int v   = e >> 5;
        const float* p = &smisc[det * 12];
        float s  = p[0];
        const float* vt = &sverts[det * SVP + 3 * v];
        float vx = vt[0], vy = vt[1], vz = vt[2];
        float l0 = s * (vx * p[1] + vy * p[2] + vz * p[3]);
        float l1 = s * (vx * p[5] + vy * p[6] + vz * p[7]);
        int idx = s_ix[det];
        int ys = idx / WW, xs = idx - (idx / WW) * WW;
        slnm[det * SLP + 2 * v]     = l1 + (float)ys * ry;
        slnm[det * SLP + 2 * v + 1] = l0 + (float)xs * rx;
    }
    __syncthreads();

    // ---- bbox min/max (warp = det; 32 warps) + pose ----
    {
        int det = wid;
        float ymn = 1e30f, ymx = -1e30f, xmn = 1e30f, xmx = -1e30f;
        for (int v = lane; v < NV; v += 32) {
            float yy = slnm[det * SLP + 2 * v];
            float xx = slnm[det * SLP + 2 * v + 1];
            ymn = fminf(ymn, yy); ymx = fmaxf(ymx, yy);
            xmn = fminf(xmn, xx); xmx = fmaxf(xmx, xx);
        }
        #pragma unroll
        for (int o = 16; o; o >>= 1) {
            ymn = fminf(ymn, __shfl_down_sync(0xffffffffu, ymn, o));
            ymx = fmaxf(ymx, __shfl_down_sync(0xffffffffu, ymx, o));
            xmn = fminf(xmn, __shfl_down_sync(0xffffffffu, xmn, o));
            xmx = fmaxf(xmx, __shfl_down_sync(0xffffffffu, xmx, o));
        }
        if (lane == 0) {
            bool mask = s_sc[det] > 0.5f;
            if (mask) { sbb[det][0] = ymn; sbb[det][1] = xmn; sbb[det][2] = ymx; sbb[det][3] = xmx; sbb[det][4] = s_sc[det]; }
            else      { sbb[det][0] = -1.0f; sbb[det][1] = -1.0f; sbb[det][2] = -1.0f; sbb[det][3] = -1.0f; sbb[det][4] = -1.0f; }

            const float* p = &smisc[det * 12];
            float yaw   = asinf(-p[9]) * RAD2DEG;
            float cyw   = cosf(yaw);   // faithful: cos of yaw in DEGREES
            float pitch = atan2f(p[10] / cyw, p[11] / cyw) * RAD2DEG;
            float roll  = atan2f(p[5] / cyw, p[1] / cyw) * RAD2DEG;
            spose[det][0] = pitch; spose[det][1] = yaw; spose[det][2] = roll;
        }
    }
    __syncthreads();

    // ---- NMS: parallel IoU row-masks + tid0 greedy bit-scan ----
    if (tid < TOPK) { sosc[tid] = 0.0f; sob[tid][0] = 0.0f; sob[tid][1] = 0.0f; sob[tid][2] = 0.0f; sob[tid][3] = 0.0f; }
    __shared__ unsigned rowm[TOPK];
    if (tid < 32) {
        int i = tid;
        float i0 = sbb[i][0], i1 = sbb[i][1], i2 = sbb[i][2], i3 = sbb[i][3];
        float ia = (i2 - i0) * (i3 - i1);
        unsigned m = 0;
        for (int j = 0; j < TOPK; j++) {
            float j0 = sbb[j][0], j1 = sbb[j][1], j2 = sbb[j][2], j3 = sbb[j][3];
            float ja = (j2 - j0) * (j3 - j1);
            float yy = fminf(i2, j2) - fmaxf(i0, j0);
            float xx = fminf(i3, j3) - fmaxf(i1, j1);
            float inter = fmaxf(yy, 0.0f) * fmaxf(xx, 0.0f);
            float uni   = ia + ja - inter;
            float iou   = inter / fmaxf(uni, 1e-8f);
            if (iou > 0.4f && j > i) m |= (1u << j);
        }
        rowm[i] = m;
    }
    __syncthreads();
    if (tid == 0) {
        unsigned supp = 0u;
        for (int i = 0; i < TOPK; i++)
            if (!((supp >> i) & 1u)) supp |= rowm[i];
        ssupp = supp;
    }
    __syncthreads();
    if (tid < 32) {
        unsigned supp = ssupp;
        bool keep = !((supp >> lane) & 1u);
        unsigned km = __ballot_sync(0xffffffffu, keep);
        int rank = __popc(km & ((1u << lane) - 1u));
        if (keep) {
            sob[rank][0] = sbb[lane][0]; sob[rank][1] = sbb[lane][1];
            sob[rank][2] = sbb[lane][2]; sob[rank][3] = sbb[lane][3];
            sosc[rank]   = sbb[lane][4];
        }
    }
    __syncthreads();

    const float INF = __int_as_float(0x7f800000);
    if (tid < TOPK) {
        bool valid = true;
        #pragma unroll
        for (int c = 0; c < 4; c++) {
            float v = sob[tid][c];
            if (v == -1.0f || v == 0.0f) { v = INF; valid = false; }
            sob[tid][c] = v;
        }
        svalid[tid] = valid ? 1 : 0;
    }
    __syncthreads();
    if (tid < TOPK) {
        float sn = s_sc[tid];
        int m = 0;
        for (int k = 0; k < TOPK; k++)
            if (svalid[k] && sosc[k] == sn) m = 1;
        smatch[tid] = m;
    }
    __syncthreads();

    // ---- pack (all from shared) ----
    float* ob = out + (size_t)b * TOPK * 6;
    for (int e = tid; e < TOPK * 6; e += 1024) {
        int k = e / 6, c = e - k * 6;
        ob[e] = (c < 4) ? sob[k][c] : ((c == 4) ? sosc[k] : 0.0f);
    }
    float* ol = out + (size_t)NB * TOPK * 6 + (size_t)b * TOPK * NV * 2;
    #pragma unroll 2
    for (int e = tid; e < TOPK * NV * 2; e += 1024) {
        int n = e / (NV * 2), j = e - n * (NV * 2);
        float l = slnm[n * SLP + j];
        ol[e] = (smatch[n] && l != -1.0f) ? l : INF;
    }
    float* op = out + (size_t)NB * TOPK * 6 + (size_t)NB * TOPK * NV * 2 + (size_t)b * TOPK * 3;
    for (int e = tid; e < TOPK * 3; e += 1024) {
        int n = e / 3, c = e - n * 3;
        float p = spose[n][c];
        op[e] = (smatch[n] && p != -1.0f) ? p : INF;
    }
}

extern "C" void kernel_launch(void* const* d_in, const int* in_sizes, int n_in,
                              void* d_out, int out_size) {
    const float* hms      = (const float*)d_in[0];
    const float* pmaps    = (const float*)d_in[1];
    const float* oshapes  = (const float*)d_in[2];
    const float* pms      = (const float*)d_in[3];
    const float* u_base   = (const float*)d_in[4];
    const float* shp_base = (const float*)d_in[5];
    const float* exp_base = (const float*)d_in[6];
    float* out = (float*)d_out;

    static int attr_done = 0;
    if (!attr_done) {
        cudaFuncSetAttribute(finish_kernel, cudaFuncAttributeMaxDynamicSharedMemorySize, F_DSM);
        attr_done = 1;
    }
    scan_kernel<<<NB * 8, 256>>>(hms, u_base, shp_base, exp_base);
    finish_kernel<<<NB, 1024, F_DSM>>>(hms, pmaps, oshapes, pms, u_base, out);
}

// round 10
// speedup vs baseline: 1.2654x; 1.0106x over previous
#include <cuda_runtime.h>
#include <math.h>

#define NB   16
#define HH   160
#define WW   160
#define HW   (HH*WW)
#define TOPK 32
#define NV   68
#define RAD2DEG 57.29577951308232f
#define GPITCH 208
#define BCAP 1024

// ---- device globals (zero-init; deterministic state across replays) ----
__device__ unsigned long long g_bandtop[NB*8*TOPK];  // fully rewritten each call
__device__ int   g_cnt[NB];          // accumulated in scan, reset in nmspack
__device__ int   g_ovf[NB];          // idem
__device__ float g_scores[NB*TOPK];  // fully rewritten each call
__device__ int   g_idxs[NB*TOPK];
__device__ float gcbT[80*GPITCH];    // transposed combined basis (rewritten each call)
__device__ float g_bbox[NB*TOPK*5];
__device__ float g_pose[NB*TOPK*3];
__device__ float g_lnm[NB*TOPK*NV*2];

// ============================================================
// Kernel 1 (128 blocks x 256): peak scan + per-band top-32 + basis transpose
// ============================================================
__global__ void __launch_bounds__(256) scan_kernel(
    const float* __restrict__ hms,
    const float* __restrict__ u_base,
    const float* __restrict__ shp_base,
    const float* __restrict__ exp_base)
{
    int blk  = blockIdx.x;
    int b    = blk >> 3;
    int band = blk & 7;
    int tid  = threadIdx.x;
    int lane = tid & 31;
    const float* h = hms + (size_t)b * HW;

    __shared__ unsigned long long bk[BCAP];
    __shared__ int s_cnt;

    if (tid == 0) s_cnt = 0;
    #pragma unroll
    for (int q = 0; q < 2; q++) {
        int r = blk + q * 128;
        if (r < 204 && tid < 80) {
            int k = tid;
            float v = (k < 50) ? shp_base[r * 50 + k]
                    : (k < 79) ? exp_base[r * 29 + (k - 50)]
                               : u_base[r];
            gcbT[k * GPITCH + r] = v;
        }
    }
    __syncthreads();

    const float NEG = -1e30f;
    for (int c = tid; c < 20 * 40; c += 256) {
        int row = c / 40;
        int x0  = (c - row * 40) * 4;
        int y   = band * 20 + row;
        int px  = y * WW + x0;
        int ym = (y > 0)      ? y - 1 : y;
        int yp = (y < HH - 1) ? y + 1 : y;
        float4 a0 = *(const float4*)(h + (size_t)ym * WW + x0);
        float4 a1 = *(const float4*)(h + (size_t)y  * WW + x0);
        float4 a2 = *(const float4*)(h + (size_t)yp * WW + x0);
        float m0 = fmaxf(a1.x, fmaxf(a0.x, a2.x));
        float m1 = fmaxf(a1.y, fmaxf(a0.y, a2.y));
        float m2 = fmaxf(a1.z, fmaxf(a0.z, a2.z));
        float m3 = fmaxf(a1.w, fmaxf(a0.w, a2.w));
        float lm = NEG, rm = NEG;
        if (x0 > 0) {
            int xl = x0 - 1;
            lm = fmaxf(h[(size_t)y * WW + xl], fmaxf(h[(size_t)ym * WW + xl], h[(size_t)yp * WW + xl]));
        }
        if (x0 + 4 < WW) {
            int xr = x0 + 4;
            rm = fmaxf(h[(size_t)y * WW + xr], fmaxf(h[(size_t)ym * WW + xr], h[(size_t)yp * WW + xr]));
        }
        float p0 = (fmaxf(lm, fmaxf(m0, m1)) == a1.x) ? a1.x : 0.0f;
        float p1 = (fmaxf(m0, fmaxf(m1, m2)) == a1.y) ? a1.y : 0.0f;
        float p2 = (fmaxf(m1, fmaxf(m2, m3)) == a1.z) ? a1.z : 0.0f;
        float p3 = (fmaxf(m2, fmaxf(m3, rm)) == a1.w) ? a1.w : 0.0f;

        float pv[4] = {p0, p1, p2, p3};
        #pragma unroll
        for (int j = 0; j < 4; j++) {
            bool has = pv[j] > 0.0f;
            unsigned bal = __ballot_sync(0xffffffffu, has);
            if (bal) {
                int leader = __ffs(bal) - 1;
                int base = 0;
                if (lane == leader) base = atomicAdd(&s_cnt, __popc(bal));
                base = __shfl_sync(0xffffffffu, base, leader);
                if (has) {
                    int pos = base + __popc(bal & ((1u << lane) - 1u));
                    if (pos < BCAP)
                        bk[pos] = ((unsigned long long)__float_as_uint(pv[j]) << 20)
                                | (unsigned)(HW - (px + j));
                }
            }
        }
    }
    __syncthreads();

    int cnt = s_cnt;
    unsigned long long* bt = &g_bandtop[(size_t)(b * 8 + band) * TOPK];
    if (tid == 0) {
        atomicAdd(&g_cnt[b], cnt);
        if (cnt > BCAP) g_ovf[b] = 1;
    }
    if (tid < TOPK) bt[tid] = 0ull;
    __syncthreads();

    if (cnt <= BCAP) {
        for (int t = tid; t < cnt; t += 256) {
            unsigned long long kt = bk[t];
            int rank = 0;
            #pragma unroll 4
            for (int i = 0; i < cnt; i++) rank += (bk[i] > kt) ? 1 : 0;
            if (rank < TOPK) bt[rank] = kt;
        }
    }
}

// ============================================================
// Kernel 2 (128 blocks x 256): redundant merge->top32 + geometry (4 dets)
// ============================================================
__global__ void __launch_bounds__(256) geom_kernel(
    const float* __restrict__ hms,
    const float* __restrict__ pmaps,
    const float* __restrict__ oshapes,
    const float* __restrict__ pms,
    const float* __restrict__ u_base)
{
    extern __shared__ float fpk[];   // HW floats; FALLBACK ONLY
    int blk  = blockIdx.x;
    int b    = blk >> 3;
    int grp  = blk & 7;
    int det0 = grp * 4;
    int tid  = threadIdx.x;
    int lane = tid & 31;
    int wid  = tid >> 5;

    __shared__ unsigned long long keys[256];
    __shared__ __align__(16) float cT[80][4];
    __shared__ float smisc[4][12];
    __shared__ float sverts[4][GPITCH];
    __shared__ float slnm[4][137];
    __shared__ float s_sc4[4];
    __shared__ int   s_ix4[4];
    __shared__ int   s_fast;
    __shared__ float rv[8];
    __shared__ int   rid[8];

    keys[tid] = g_bandtop[(size_t)b * 256 + tid];
    if (tid == 0) s_fast = (g_cnt[b] >= TOPK && !g_ovf[b]) ? 1 : 0;
    __syncthreads();

    if (s_fast) {
        // every block ranks all 256 keys; owner writes its dets
        unsigned long long kt = keys[tid];
        int rank = 0;
        #pragma unroll 8
        for (int i = 0; i < 256; i++) rank += (keys[i] > kt) ? 1 : 0;
        if (rank < TOPK && (rank >> 2) == grp) {
            float sc = __uint_as_float((unsigned)(kt >> 20));
            int   ix = HW - (int)(kt & 0xFFFFFull);
            s_sc4[rank & 3] = sc;
            s_ix4[rank & 3] = ix;
            g_scores[b * TOPK + rank] = sc;
            g_idxs[b * TOPK + rank]   = ix;
        }
    } else {
        // robust fallback: full peak map in dynamic shared + 32 argmax rounds
        const float* h = hms + (size_t)b * HW;
        for (int i = tid; i < HW; i += 256) {
            int y = i / WW, x = i - y * WW;
            float v = h[i], m = v;
            int y0 = (y > 0) ? y - 1 : y, y1 = (y < HH - 1) ? y + 1 : y;
            int x0 = (x > 0) ? x - 1 : x, x1 = (x < WW - 1) ? x + 1 : x;
            for (int yy = y0; yy <= y1; yy++)
                for (int xx = x0; xx <= x1; xx++)
                    m = fmaxf(m, h[yy * WW + xx]);
            fpk[i] = (v == m) ? v : 0.0f;
        }
        __syncthreads();
        for (int r = 0; r < TOPK; r++) {
            float bv = -2.0f; int bi = 0x3fffffff;
            for (int i = tid; i < HW; i += 256) {
                float v = fpk[i];
                if (v > bv || (v == bv && i < bi)) { bv = v; bi = i; }
            }
            #pragma unroll
            for (int o = 16; o; o >>= 1) {
                float v2 = __shfl_down_sync(0xffffffffu, bv, o);
                int   i2 = __shfl_down_sync(0xffffffffu, bi, o);
                if (v2 > bv || (v2 == bv && i2 < bi)) { bv = v2; bi = i2; }
            }
            if (lane == 0) { rv[wid] = bv; rid[wid] = bi; }
            __syncthreads();
            if (tid < 8) {
                bv = rv[tid]; bi = rid[tid];
                #pragma unroll
                for (int o = 4; o; o >>= 1) {
                    float v2 = __shfl_down_sync(0xffu, bv, o);
                    int   i2 = __shfl_down_sync(0xffu, bi, o);
                    if (v2 > bv || (v2 == bv && i2 < bi)) { bv = v2; bi = i2; }
                }
                if (tid == 0) {
                    if ((r >> 2) == grp) {
                        s_sc4[r & 3] = bv; s_ix4[r & 3] = bi;
                        g_scores[b * TOPK + r] = bv;
                        g_idxs[b * TOPK + r]   = bi;
                    }
                    fpk[bi] = -1.0f;
                }
            }
            __syncthreads();
        }
    }
    __syncthreads();

    // ---- geometry for 4 dets ----
    for (int e = tid; e < 4 * 91; e += 256) {
        int det = e / 91, j = e - det * 91;
        float v = fmaf(pmaps[((size_t)b * HW + (size_t)s_ix4[det]) * 91 + j],
                       pms[91 + j], pms[j]);
        if (j < 12)      smisc[det][j] = v;
        else if (j < 62) cT[j - 12][det] = v;
        else             cT[50 + (j - 62)][det] = v;
    }
    __syncthreads();

    if (tid < 204) {
        int row = tid;
        float u = u_base[row];
        float a0 = u, a1 = u, a2 = u, a3 = u;
        #pragma unroll 4
        for (int k = 0; k < 79; k++) {
            float bv = gcbT[k * GPITCH + row];
            float4 c = *(const float4*)&cT[k][0];
            a0 = fmaf(bv, c.x, a0);
            a1 = fmaf(bv, c.y, a1);
            a2 = fmaf(bv, c.z, a2);
            a3 = fmaf(bv, c.w, a3);
        }
        sverts[0][row] = a0;
        sverts[1][row] = a1;
        sverts[2][row] = a2;
        sverts[3][row] = a3;
    }
    __syncthreads();

    float ry = oshapes[b * 2 + 0] * (1.0f / 160.0f);
    float rx = oshapes[b * 2 + 1] * (1.0f / 160.0f);
    for (int e = tid; e < 4 * NV; e += 256) {
        int det = e / NV, v = e - det * NV;
        const float* p = smisc[det];
        float s  = p[0];
        float vx = sverts[det][3 * v], vy = sverts[det][3 * v + 1], vz = sverts[det][3 * v + 2];
        float l0 = s * (vx * p[1] + vy * p[2] + vz * p[3]);
        float l1 = s * (vx * p[5] + vy * p[6] + vz * p[7]);
        int idx = s_ix4[det];
        int ys = idx / WW, xs = idx - (idx / WW) * WW;
        float yy = l1 + (float)ys * ry;
        float xx = l0 + (float)xs * rx;
        slnm[det][2 * v]     = yy;
        slnm[det][2 * v + 1] = xx;
        size_t gd = (size_t)(b * TOPK + det0 + det);
        g_lnm[(gd * NV + v) * 2 + 0] = yy;
        g_lnm[(gd * NV + v) * 2 + 1] = xx;
    }
    __syncthreads();

    if (wid < 4) {
        int det = wid;
        float ymn = 1e30f, ymx = -1e30f, xmn = 1e30f, xmx = -1e30f;
        for (int v = lane; v < NV; v += 32) {
            float yy = slnm[det][2 * v], xx = slnm[det][2 * v + 1];
            ymn = fminf(ymn, yy); ymx = fmaxf(ymx, yy);
            xmn = fminf(xmn, xx); xmx = fmaxf(xmx, xx);
        }
        #pragma unroll
        for (int o = 16; o; o >>= 1) {
            ymn = fminf(ymn, __shfl_down_sync(0xffffffffu, ymn, o));
            ymx = fmaxf(ymx, __shfl_down_sync(0xffffffffu, ymx, o));
            xmn = fminf(xmn, __shfl_down_sync(0xffffffffu, xmn, o));
            xmx = fmaxf(xmx, __shfl_down_sync(0xffffffffu, xmx, o));
        }
        if (lane == 0) {
            size_t gd = (size_t)(b * TOPK + det0 + det);
            bool mask = s_sc4[det] > 0.5f;
            float* bb = g_bbox + gd * 5;
            if (mask) { bb[0] = ymn; bb[1] = xmn; bb[2] = ymx; bb[3] = xmx; bb[4] = s_sc4[det]; }
            else      { bb[0] = -1.0f; bb[1] = -1.0f; bb[2] = -1.0f; bb[3] = -1.0f; bb[4] = -1.0f; }

            const float* p = smisc[det];
            float yaw   = asinf(-p[9]) * RAD2DEG;
            float cyw   = cosf(yaw);   // faithful: cos of yaw in DEGREES
            float pitch = atan2f(p[10] / cyw, p[11] / cyw) * RAD2DEG;
            float roll  = atan2f(p[5] / cyw, p[1] / cyw) * RAD2DEG;
            float* pp = g_pose + gd * 3;
            pp[0] = pitch; pp[1] = yaw; pp[2] = roll;
        }
    }
}

// ============================================================
// Kernel 3 (128 blocks x 256): redundant NMS + strided pack (1/8 per block)
// ============================================================
__global__ void __launch_bounds__(256) nmspack_kernel(float* __restrict__ out) {
    int blk  = blockIdx.x;
    int b    = blk >> 3;
    int part = blk & 7;
    int tid  = threadIdx.x;
    int lane = tid & 31;

    __shared__ float sbb[TOPK][5];
    __shared__ float sscore[TOPK];
    __shared__ float sob[TOPK][4], sosc[TOPK];
    __shared__ unsigned rowm[TOPK];
    __shared__ unsigned ssupp;
    __shared__ int svalid[TOPK], smatch[TOPK];

    if (tid < TOPK * 5) {
        int k = tid / 5, c = tid - k * 5;
        sbb[k][c] = g_bbox[((size_t)b * TOPK + k) * 5 + c];
    }
    if (tid >= 192 && tid < 192 + TOPK) {
        int k = tid - 192;
        sscore[k] = g_scores[b * TOPK + k];
        sosc[k] = 0.0f;
        sob[k][0] = 0.0f; sob[k][1] = 0.0f; sob[k][2] = 0.0f; sob[k][3] = 0.0f;
    }
    if (tid == 0 && part == 0) { g_cnt[b] = 0; g_ovf[b] = 0; }  // restore zero-state
    __syncthreads();

    if (tid < 32) {
        int i = tid;
        float i0 = sbb[i][0], i1 = sbb[i][1], i2 = sbb[i][2], i3 = sbb[i][3];
        float ia = (i2 - i0) * (i3 - i1);
        unsigned m = 0;
        for (int j = 0; j < TOPK; j++) {
            float j0 = sbb[j][0], j1 = sbb[j][1], j2 = sbb[j][2], j3 = sbb[j][3];
            float ja = (j2 - j0) * (j3 - j1);
            float yy = fminf(i2, j2) - fmaxf(i0, j0);
            float xx = fminf(i3, j3) - fmaxf(i1, j1);
            float inter = fmaxf(yy, 0.0f) * fmaxf(xx, 0.0f);
            float uni   = ia + ja - inter;
            float iou   = inter / fmaxf(uni, 1e-8f);
            if (iou > 0.4f && j > i) m |= (1u << j);
        }
        rowm[i] = m;
    }
    __syncthreads();
    if (tid == 0) {
        unsigned supp = 0u;
        for (int i = 0; i < TOPK; i++)
            if (!((supp >> i) & 1u)) supp |= rowm[i];
        ssupp = supp;
    }
    __syncthreads();
    if (tid < 32) {
        unsigned supp = ssupp;
        bool keep = !((supp >> lane) & 1u);
        unsigned km = __ballot_sync(0xffffffffu, keep);
        int rank = __popc(km & ((1u << lane) - 1u));
        if (keep) {
            sob[rank][0] = sbb[lane][0]; sob[rank][1] = sbb[lane][1];
            sob[rank][2] = sbb[lane][2]; sob[rank][3] = sbb[lane][3];
            sosc[rank]   = sbb[lane][4];
        }
    }
    __syncthreads();

    const float INF = __int_as_float(0x7f800000);
    if (tid < TOPK) {
        bool valid = true;
        #pragma unroll
        for (int c = 0; c < 4; c++) {
            float v = sob[tid][c];
            if (v == -1.0f || v == 0.0f) { v = INF; valid = false; }
            sob[tid][c] = v;
        }
        svalid[tid] = valid ? 1 : 0;
    }
    __syncthreads();
    if (tid < TOPK) {
        float sn = sscore[tid];
        int m = 0;
        for (int k = 0; k < TOPK; k++)
            if (svalid[k] && sosc[k] == sn) m = 1;
        smatch[tid] = m;
    }
    __syncthreads();

    // ---- strided pack: this block writes the (part*256+tid) mod 2048 lanes ----
    float* ob = out + (size_t)b * TOPK * 6;
    for (int e = part * 256 + tid; e < TOPK * 6; e += 2048) {
        int k = e / 6, c = e - k * 6;
        ob[e] = (c < 4) ? sob[k][c] : ((c == 4) ? sosc[k] : 0.0f);
    }
    float* ol = out + (size_t)NB * TOPK * 6 + (size_t)b * TOPK * NV * 2;
    for (int e = part * 256 + tid; e < TOPK * NV * 2; e += 2048) {
        int n = e / (NV * 2);
        float l = g_lnm[(size_t)b * TOPK * NV * 2 + e];
        ol[e] = (smatch[n] && l != -1.0f) ? l : INF;
    }
    float* op = out + (size_t)NB * TOPK * 6 + (size_t)NB * TOPK * NV * 2 + (size_t)b * TOPK * 3;
    for (int e = part * 256 + tid; e < TOPK * 3; e += 2048) {
        int n = e / 3;
        float p = g_pose[(size_t)b * TOPK * 3 + e];
        op[e] = (smatch[n] && p != -1.0f) ? p : INF;
    }
}

extern "C" void kernel_launch(void* const* d_in, const int* in_sizes, int n_in,
                              void* d_out, int out_size) {
    const float* hms      = (const float*)d_in[0];
    const float* pmaps    = (const float*)d_in[1];
    const float* oshapes  = (const float*)d_in[2];
    const float* pms      = (const float*)d_in[3];
    const float* u_base   = (const float*)d_in[4];
    const float* shp_base = (const float*)d_in[5];
    const float* exp_base = (const float*)d_in[6];
    float* out = (float*)d_out;

    static int attr_done = 0;
    if (!attr_done) {
        cudaFuncSetAttribute(geom_kernel, cudaFuncAttributeMaxDynamicSharedMemorySize, HW * 4);
        attr_done = 1;
    }
    scan_kernel<<<128, 256>>>(hms, u_base, shp_base, exp_base);
    geom_kernel<<<128, 256, HW * 4>>>(hms, pmaps, oshapes, pms, u_base);
    nmspack_kernel<<<128, 256>>>(out);
}